// round 9
// baseline (speedup 1.0000x reference)
#include <cuda_runtime.h>
#include <cuda_bf16.h>

// Problem constants
#define B_   8
#define S1_  512
#define S2_  512
#define HID_ 128
#define HD_  128
#define TSPLIT 8
#define VSPLIT 4

// ---------------- scratch (static device memory; no allocations) -------------
__device__ float g_qp  [B_ * S1_ * HID_];                 // 2 MB
__device__ float g_kp  [B_ * S2_ * HID_];                 // 2 MB
__device__ float g_a   [B_ * S1_];                        // 0.5*qp.W2 + b2
__device__ float g_c   [B_ * S2_];                        // 0.5*kp.W2 (or -1e30 if masked)
__device__ float g_p   [B_ * S1_ * S2_];                  // 8 MB masked exp scores
__device__ float g_pout[VSPLIT * B_ * S1_ * HD_];         // 8 MB value partials
__device__ float g_pden[TSPLIT * B_ * S1_];               // denominator partials

// ---------------- packed f32x2 helpers (Blackwell-only PTX) ------------------
__device__ __forceinline__ unsigned long long f32x2_add(unsigned long long a,
                                                        unsigned long long b) {
    unsigned long long r;
    asm("add.rn.f32x2 %0, %1, %2;" : "=l"(r) : "l"(a), "l"(b));
    return r;
}
__device__ __forceinline__ unsigned long long f32x2_fma(unsigned long long a,
                                                        unsigned long long b,
                                                        unsigned long long c) {
    unsigned long long r;
    asm("fma.rn.f32x2 %0, %1, %2, %3;" : "=l"(r) : "l"(a), "l"(b), "l"(c));
    return r;
}
__device__ __forceinline__ unsigned long long f32x2_pack(float lo, float hi) {
    unsigned long long r;
    asm("mov.b64 %0, {%1, %2};" : "=l"(r) : "f"(lo), "f"(hi));
    return r;
}
__device__ __forceinline__ void f32x2_unpack(unsigned long long a, float& lo, float& hi) {
    asm("mov.b64 {%0, %1}, %2;" : "=f"(lo), "=f"(hi) : "l"(a));
}
__device__ __forceinline__ float bfly_step(float keep, float send, int off) {
    return keep + __shfl_xor_sync(0xffffffffu, send, off);
}

// ================= Kernel 1: projections qp / kp + linear score terms ========
// (R4 version — measured 17.8us.) grid (128, 2), block 256. 32-row tiles,
// register double-buffered across kc chunks; packed f32x2 inner product.
__global__ __launch_bounds__(256) void proj_kernel(
    const float* __restrict__ query, const float* __restrict__ key,
    const float* __restrict__ W1, const float* __restrict__ b1,
    const float* __restrict__ W2, const float* __restrict__ b2,
    const int* __restrict__ k_mask)
{
    __shared__ float xs[32][33];
    __shared__ float ws[32][132];

    const int tid = threadIdx.x;
    const int tx = tid & 31;
    const int ty = tid >> 5;
    const int R0 = blockIdx.x * 32;
    const int part = blockIdx.y;
    const float* X = part ? key : query;
    float* out = part ? g_kp : g_qp;
    const int woff = part * 128;

    unsigned long long acc2[4][2];
    if (part == 0) {
        float4 bv = *reinterpret_cast<const float4*>(b1 + tx * 4);
        unsigned long long b01 = f32x2_pack(bv.x, bv.y);
        unsigned long long b23 = f32x2_pack(bv.z, bv.w);
        #pragma unroll
        for (int i = 0; i < 4; i++) { acc2[i][0] = b01; acc2[i][1] = b23; }
    } else {
        #pragma unroll
        for (int i = 0; i < 4; i++) { acc2[i][0] = 0ULL; acc2[i][1] = 0ULL; }
    }

    const int xr = tid >> 3, xk = (tid & 7) * 4;

    float4 xreg = *reinterpret_cast<const float4*>(X + (size_t)(R0 + xr) * 128 + xk);
    float4 wreg[4];
    #pragma unroll
    for (int j = 0; j < 4; j++) {
        int idx = tid + j * 256;
        int h = idx >> 3, k4 = (idx & 7) * 4;
        wreg[j] = *reinterpret_cast<const float4*>(W1 + (size_t)h * 256 + woff + k4);
    }

    for (int kc = 0; kc < 4; kc++) {
        xs[xr][xk + 0] = xreg.x; xs[xr][xk + 1] = xreg.y;
        xs[xr][xk + 2] = xreg.z; xs[xr][xk + 3] = xreg.w;
        #pragma unroll
        for (int j = 0; j < 4; j++) {
            int idx = tid + j * 256;
            int h = idx >> 3, k4 = (idx & 7) * 4;
            ws[k4 + 0][h] = wreg[j].x; ws[k4 + 1][h] = wreg[j].y;
            ws[k4 + 2][h] = wreg[j].z; ws[k4 + 3][h] = wreg[j].w;
        }
        __syncthreads();

        if (kc < 3) {
            xreg = *reinterpret_cast<const float4*>(
                X + (size_t)(R0 + xr) * 128 + (kc + 1) * 32 + xk);
            #pragma unroll
            for (int j = 0; j < 4; j++) {
                int idx = tid + j * 256;
                int h = idx >> 3, k4 = (idx & 7) * 4;
                wreg[j] = *reinterpret_cast<const float4*>(
                    W1 + (size_t)h * 256 + woff + (kc + 1) * 32 + k4);
            }
        }

        #pragma unroll 8
        for (int k = 0; k < 32; k++) {
            ulonglong2 wv2 = *reinterpret_cast<const ulonglong2*>(&ws[k][tx * 4]);
            #pragma unroll
            for (int i = 0; i < 4; i++) {
                float xv = xs[ty + 8 * i][k];
                unsigned long long xx = f32x2_pack(xv, xv);
                acc2[i][0] = f32x2_fma(wv2.x, xx, acc2[i][0]);
                acc2[i][1] = f32x2_fma(wv2.y, xx, acc2[i][1]);
            }
        }
        __syncthreads();
    }

    float4 accf[4];
    #pragma unroll
    for (int i = 0; i < 4; i++) {
        f32x2_unpack(acc2[i][0], accf[i].x, accf[i].y);
        f32x2_unpack(acc2[i][1], accf[i].z, accf[i].w);
        int r = R0 + ty + 8 * i;
        *reinterpret_cast<float4*>(out + (size_t)r * 128 + tx * 4) = accf[i];
    }

    float4 w2v = *reinterpret_cast<const float4*>(W2 + tx * 4);
    #pragma unroll
    for (int i = 0; i < 4; i++) {
        float ps = accf[i].x * w2v.x + accf[i].y * w2v.y
                 + accf[i].z * w2v.z + accf[i].w * w2v.w;
        #pragma unroll
        for (int off = 16; off >= 1; off >>= 1)
            ps += __shfl_xor_sync(0xffffffffu, ps, off);
        if (tx == 0) {
            int r = R0 + ty + 8 * i;
            if (part == 0) {
                g_a[r] = 0.5f * ps + b2[0];
            } else {
                g_c[r] = k_mask[r] ? 0.5f * ps : -1e30f;
            }
        }
    }
}

// ================= Kernel 2: score + exp + mask -> g_p, den partials =========
// s[b,s,t] = a_s + c_t + sum_h 0.5*W2_h*|qp_h + kp_h|   (relu identity)
// grid (S1/64, TSPLIT, B), block 256. Warp covers 8 s (sets A/B). tt processed
// in groups of 8 with a butterfly transpose-reduction: lane hc ends with the
// full score for tt = g*8+hc (exp runs once per 8 tt). p written coalesced.
__global__ __launch_bounds__(256, 4) void score_kernel(const float* __restrict__ W2)
{
    __shared__ float kp_s[32 * 128];   // permuted: chunk (hc, ib) at slot ib*8+hc
    __shared__ float c_s [32];

    const int tid = threadIdx.x;
    const int warp = tid >> 5, lane = tid & 31;
    const int s_local = lane >> 3, hc = lane & 7;
    const int stile = blockIdx.x, tz = blockIdx.y, b = blockIdx.z;
    const int sA = stile * 64 + warp * 8 + s_local;
    const int sB = sA + 4;
    const int rowA = b * S1_ + sA;
    const int rowB = b * S1_ + sB;

    unsigned long long qpA2[8], qpB2[8], w2p[8];
    {
        const float4* qrowA = reinterpret_cast<const float4*>(
            g_qp + (size_t)rowA * HID_ + hc * 16);
        const float4* qrowB = reinterpret_cast<const float4*>(
            g_qp + (size_t)rowB * HID_ + hc * 16);
        #pragma unroll
        for (int i = 0; i < 4; i++) {
            float4 qa = qrowA[i];
            qpA2[2 * i]     = f32x2_pack(qa.x, qa.y);
            qpA2[2 * i + 1] = f32x2_pack(qa.z, qa.w);
            float4 qb = qrowB[i];
            qpB2[2 * i]     = f32x2_pack(qb.x, qb.y);
            qpB2[2 * i + 1] = f32x2_pack(qb.z, qb.w);
            float4 w = *reinterpret_cast<const float4*>(W2 + hc * 16 + i * 4);
            w2p[2 * i]     = f32x2_pack(0.5f * w.x, 0.5f * w.y);
            w2p[2 * i + 1] = f32x2_pack(0.5f * w.z, 0.5f * w.w);
        }
    }
    const float aA = g_a[rowA];
    const float aB = g_a[rowB];

    float denA = 0.f, denB = 0.f;        // lane-distributed over tt (disjoint)

    const int t0 = tz * (S2_ / TSPLIT);
    const unsigned long long ABS2 = 0x7FFFFFFF7FFFFFFFULL;
    const int bit0 = hc & 1, bit1 = (hc >> 1) & 1, bit2 = (hc >> 2) & 1;

    for (int chunk = 0; chunk < (S2_ / TSPLIT) / 32; chunk++) {
        const int tbase = t0 + chunk * 32;
        __syncthreads();
        #pragma unroll
        for (int j = 0; j < 4; j++) {
            int idx = tid + j * 256;            // 0..1023 float4s
            int tt = idx >> 5, l = idx & 31;
            int h4 = ((l & 7) << 2) | (l >> 3); // inverse of slot permutation
            const float4* krow = reinterpret_cast<const float4*>(
                g_kp + (size_t)(b * S2_ + tbase + tt) * HID_);
            reinterpret_cast<float4*>(kp_s)[tt * 32 + l] = krow[h4];
        }
        if (tid < 32) c_s[tid] = g_c[b * S2_ + tbase + tid];
        __syncthreads();

        #pragma unroll 1
        for (int g = 0; g < 4; g++) {
            float rA[4], rB[4];
            #pragma unroll
            for (int k = 0; k < 4; k++) {
                float m0A, m0B, m1A, m1B;
                #pragma unroll
                for (int half = 0; half < 2; half++) {
                    const float* kprow = kp_s + (g * 8 + 2 * k + half) * 128;
                    unsigned long long a0 = 0ULL, a1 = 0ULL, b0 = 0ULL, b1 = 0ULL;
                    #pragma unroll
                    for (int ib = 0; ib < 4; ib++) {
                        ulonglong2 kv = *reinterpret_cast<const ulonglong2*>(
                            kprow + ib * 32 + hc * 4);
                        unsigned long long xA01 = f32x2_add(qpA2[2 * ib],     kv.x) & ABS2;
                        unsigned long long xA23 = f32x2_add(qpA2[2 * ib + 1], kv.y) & ABS2;
                        unsigned long long xB01 = f32x2_add(qpB2[2 * ib],     kv.x) & ABS2;
                        unsigned long long xB23 = f32x2_add(qpB2[2 * ib + 1], kv.y) & ABS2;
                        a0 = f32x2_fma(xA01, w2p[2 * ib],     a0);
                        a1 = f32x2_fma(xA23, w2p[2 * ib + 1], a1);
                        b0 = f32x2_fma(xB01, w2p[2 * ib],     b0);
                        b1 = f32x2_fma(xB23, w2p[2 * ib + 1], b1);
                    }
                    float la, ha, lb, hb;
                    f32x2_unpack(f32x2_add(a0, a1), la, ha);
                    f32x2_unpack(f32x2_add(b0, b1), lb, hb);
                    if (half == 0) { m0A = la + ha; m0B = lb + hb; }
                    else           { m1A = la + ha; m1B = lb + hb; }
                }
                rA[k] = bfly_step(bit0 ? m1A : m0A, bit0 ? m0A : m1A, 1);
                rB[k] = bfly_step(bit0 ? m1B : m0B, bit0 ? m0B : m1B, 1);
            }
            float sA2[2], sB2[2];
            #pragma unroll
            for (int k = 0; k < 2; k++) {
                sA2[k] = bfly_step(bit1 ? rA[2 * k + 1] : rA[2 * k],
                                   bit1 ? rA[2 * k] : rA[2 * k + 1], 2);
                sB2[k] = bfly_step(bit1 ? rB[2 * k + 1] : rB[2 * k],
                                   bit1 ? rB[2 * k] : rB[2 * k + 1], 2);
            }
            float scA = bfly_step(bit2 ? sA2[1] : sA2[0],
                                  bit2 ? sA2[0] : sA2[1], 4);
            float scB = bfly_step(bit2 ? sB2[1] : sB2[0],
                                  bit2 ? sB2[0] : sB2[1], 4);

            float ct = c_s[g * 8 + hc];
            float pA = __expf(scA + aA + ct);   // c = -1e30 => p = 0 (mask)
            float pB = __expf(scB + aB + ct);
            denA += pA;
            denB += pB;

            // coalesced p writes: 8 lanes of a given s write 8 consecutive t
            int t = tbase + g * 8 + hc;
            g_p[(size_t)rowA * S2_ + t] = pA;
            g_p[(size_t)rowB * S2_ + t] = pB;
        }
    }

    #pragma unroll
    for (int off = 1; off <= 4; off <<= 1) {
        denA += __shfl_xor_sync(0xffffffffu, denA, off);
        denB += __shfl_xor_sync(0xffffffffu, denB, off);
    }
    if (hc == 0) {
        g_pden[(size_t)(tz * B_ + b) * S1_ + sA] = denA;
        g_pden[(size_t)(tz * B_ + b) * S1_ + sB] = denB;
    }
}

// ================= Kernel 3: value GEMM  out_part = p @ V ====================
// grid (S1/64, VSPLIT, B), block 256. Tile 64 s x 128 d, t-chunk 16.
// Thread (ty=tid>>5, tx=tid&31): rows ty+8i, cols tx*4..+3 (packed f32x2).
__global__ __launch_bounds__(256, 3) void value_kernel(const float* __restrict__ value)
{
    __shared__ float p_s[64][20];       // 80B row stride
    __shared__ float v_s[16][128];

    const int tid = threadIdx.x;
    const int tx = tid & 31, ty = tid >> 5;
    const int S0 = blockIdx.x * 64, tz = blockIdx.y, b = blockIdx.z;
    const int tv0 = tz * (S2_ / VSPLIT);

    unsigned long long acc[8][2];
    #pragma unroll
    for (int i = 0; i < 8; i++) { acc[i][0] = 0ULL; acc[i][1] = 0ULL; }

    for (int ch = 0; ch < (S2_ / VSPLIT) / 16; ch++) {
        const int tb = tv0 + ch * 16;
        __syncthreads();
        {   // p tile 64 x 16 : one float4 per thread
            int s = tid >> 2, t4 = (tid & 3) * 4;
            *reinterpret_cast<float4*>(&p_s[s][t4]) =
                *reinterpret_cast<const float4*>(
                    g_p + (size_t)(b * S1_ + S0 + s) * S2_ + tb + t4);
        }
        #pragma unroll
        for (int j = 0; j < 2; j++) {   // v tile 16 x 128 : two float4s/thread
            int idx = tid + j * 256;
            int t = idx >> 5, c = (idx & 31) * 4;
            *reinterpret_cast<float4*>(&v_s[t][c]) =
                *reinterpret_cast<const float4*>(
                    value + (size_t)(b * S2_ + tb + t) * HD_ + c);
        }
        __syncthreads();

        #pragma unroll
        for (int q = 0; q < 4; q++) {
            float4 pv[8];
            #pragma unroll
            for (int i = 0; i < 8; i++)
                pv[i] = *reinterpret_cast<const float4*>(&p_s[ty + 8 * i][q * 4]);
            #pragma unroll
            for (int kk = 0; kk < 4; kk++) {
                float4 vv = *reinterpret_cast<const float4*>(&v_s[q * 4 + kk][tx * 4]);
                unsigned long long v01 = f32x2_pack(vv.x, vv.y);
                unsigned long long v23 = f32x2_pack(vv.z, vv.w);
                #pragma unroll
                for (int i = 0; i < 8; i++) {
                    float pf = (kk == 0) ? pv[i].x : (kk == 1) ? pv[i].y
                             : (kk == 2) ? pv[i].z : pv[i].w;
                    unsigned long long pp = f32x2_pack(pf, pf);
                    acc[i][0] = f32x2_fma(v01, pp, acc[i][0]);
                    acc[i][1] = f32x2_fma(v23, pp, acc[i][1]);
                }
            }
        }
    }

    #pragma unroll
    for (int i = 0; i < 8; i++) {
        float4 f;
        f32x2_unpack(acc[i][0], f.x, f.y);
        f32x2_unpack(acc[i][1], f.z, f.w);
        int row = S0 + ty + 8 * i;
        *reinterpret_cast<float4*>(
            g_pout + ((size_t)(tz * B_ + b) * S1_ + row) * HD_ + tx * 4) = f;
    }
}

// ================= Kernel 4: reduce partials + normalize + q_mask ============
__global__ __launch_bounds__(256) void reduce_kernel(
    const int* __restrict__ q_mask, float* __restrict__ out)
{
    int idx = blockIdx.x * 256 + threadIdx.x;   // float4 index
    if (idx >= B_ * S1_ * (HD_ / 4)) return;
    int d4 = idx & 31;
    int row = idx >> 5;                          // b*S1 + s
    float4 sum = make_float4(0.f, 0.f, 0.f, 0.f);
    float dsum = 0.f;
    #pragma unroll
    for (int k = 0; k < VSPLIT; k++) {
        float4 p = reinterpret_cast<const float4*>(g_pout)
                       [((size_t)k * B_ * S1_ + row) * 32 + d4];
        sum.x += p.x; sum.y += p.y; sum.z += p.z; sum.w += p.w;
    }
    #pragma unroll
    for (int k = 0; k < TSPLIT; k++)
        dsum += g_pden[(size_t)k * B_ * S1_ + row];
    float qm = (float)q_mask[row];
    float scale = qm / fmaxf(dsum, 2e-15f);
    reinterpret_cast<float4*>(out)[idx] =
        make_float4(sum.x * scale, sum.y * scale, sum.z * scale, sum.w * scale);
}

// ================= launch ====================================================
extern "C" void kernel_launch(void* const* d_in, const int* in_sizes, int n_in,
                              void* d_out, int out_size)
{
    const float* query  = (const float*)d_in[0];
    const float* key    = (const float*)d_in[1];
    const float* value  = (const float*)d_in[2];
    const int*   q_mask = (const int*)  d_in[3];
    const int*   k_mask = (const int*)  d_in[4];
    const float* W1     = (const float*)d_in[5];
    const float* b1     = (const float*)d_in[6];
    const float* W2     = (const float*)d_in[7];
    const float* b2     = (const float*)d_in[8];
    float* out = (float*)d_out;

    proj_kernel  <<<dim3(128, 2), 256>>>(query, key, W1, b1, W2, b2, k_mask);
    score_kernel <<<dim3(S1_ / 64, TSPLIT, B_), 256>>>(W2);
    value_kernel <<<dim3(S1_ / 64, VSPLIT, B_), 256>>>(value);
    reduce_kernel<<<(B_ * S1_ * (HD_ / 4) + 255) / 256, 256>>>(q_mask, out);
}

// round 11
// speedup vs baseline: 2.0115x; 2.0115x over previous
#include <cuda_runtime.h>
#include <cuda_bf16.h>

// Problem constants
#define B_   8
#define S1_  512
#define S2_  512
#define HID_ 128
#define HD_  128
#define TSPLIT 8

// ---------------- scratch (static device memory; no allocations) -------------
__device__ float g_qp  [B_ * S1_ * HID_];                 // 2 MB
__device__ float g_kp  [B_ * S2_ * HID_];                 // 2 MB
__device__ float g_a   [B_ * S1_];                        // 0.5*qp.W2 + b2
__device__ float g_c   [B_ * S2_];                        // 0.5*kp.W2 (or -1e30 if masked)
__device__ int   g_slist[B_ * S1_];                       // compacted active s ids
__device__ int   g_tlist[B_ * S2_];                       // compacted active t ids
__device__ int   g_ns[B_], g_nt[B_];
__device__ float g_pout[TSPLIT * B_ * S1_ * HD_];         // 16 MB value partials
__device__ float g_pden[TSPLIT * B_ * S1_];               // denominator partials

// ---------------- packed f32x2 helpers (Blackwell-only PTX) ------------------
__device__ __forceinline__ unsigned long long f32x2_add(unsigned long long a,
                                                        unsigned long long b) {
    unsigned long long r;
    asm("add.rn.f32x2 %0, %1, %2;" : "=l"(r) : "l"(a), "l"(b));
    return r;
}
__device__ __forceinline__ unsigned long long f32x2_fma(unsigned long long a,
                                                        unsigned long long b,
                                                        unsigned long long c) {
    unsigned long long r;
    asm("fma.rn.f32x2 %0, %1, %2, %3;" : "=l"(r) : "l"(a), "l"(b), "l"(c));
    return r;
}
__device__ __forceinline__ unsigned long long f32x2_pack(float lo, float hi) {
    unsigned long long r;
    asm("mov.b64 %0, {%1, %2};" : "=l"(r) : "f"(lo), "f"(hi));
    return r;
}
__device__ __forceinline__ void f32x2_unpack(unsigned long long a, float& lo, float& hi) {
    asm("mov.b64 {%0, %1}, %2;" : "=f"(lo), "=f"(hi) : "l"(a));
}
__device__ __forceinline__ float bfly_step(float keep, float send, int off) {
    return keep + __shfl_xor_sync(0xffffffffu, send, off);
}

// ================= Kernel 0: compact active s / t index lists ================
// One block per batch, 512 threads. Deterministic ballot+scan compaction.
__global__ __launch_bounds__(512) void compact_kernel(
    const int* __restrict__ q_mask, const int* __restrict__ k_mask)
{
    __shared__ int wcnt[16], woff[16];
    __shared__ int total_sh;
    const int b = blockIdx.x, tid = threadIdx.x;
    const int lane = tid & 31, wid = tid >> 5;

    // ---- t side (k_mask) ----
    int m = k_mask[b * S2_ + tid] != 0;
    unsigned bal = __ballot_sync(0xffffffffu, m);
    if (lane == 0) wcnt[wid] = __popc(bal);
    __syncthreads();
    if (tid == 0) {
        int acc = 0;
        for (int i = 0; i < 16; i++) { woff[i] = acc; acc += wcnt[i]; }
        total_sh = acc;
    }
    __syncthreads();
    int pos = woff[wid] + __popc(bal & ((1u << lane) - 1));
    if (m) g_tlist[b * S2_ + pos] = tid;
    int ntv = total_sh;
    if (tid == 0) g_nt[b] = ntv;
    for (int j = ntv + tid; j < S2_; j += 512) g_tlist[b * S2_ + j] = 0;
    __syncthreads();

    // ---- s side (q_mask) ----
    m = q_mask[b * S1_ + tid] != 0;
    bal = __ballot_sync(0xffffffffu, m);
    if (lane == 0) wcnt[wid] = __popc(bal);
    __syncthreads();
    if (tid == 0) {
        int acc = 0;
        for (int i = 0; i < 16; i++) { woff[i] = acc; acc += wcnt[i]; }
        total_sh = acc;
    }
    __syncthreads();
    pos = woff[wid] + __popc(bal & ((1u << lane) - 1));
    if (m) g_slist[b * S1_ + pos] = tid;
    int nsv = total_sh;
    if (tid == 0) g_ns[b] = nsv;
    for (int j = nsv + tid; j < S1_; j += 512) g_slist[b * S1_ + j] = 0;
}

// ================= Kernel 1: projections qp / kp + linear score terms ========
// (R4 version — measured 17.8us.) grid (128, 2), block 256.
__global__ __launch_bounds__(256) void proj_kernel(
    const float* __restrict__ query, const float* __restrict__ key,
    const float* __restrict__ W1, const float* __restrict__ b1,
    const float* __restrict__ W2, const float* __restrict__ b2,
    const int* __restrict__ k_mask)
{
    __shared__ float xs[32][33];
    __shared__ float ws[32][132];

    const int tid = threadIdx.x;
    const int tx = tid & 31;
    const int ty = tid >> 5;
    const int R0 = blockIdx.x * 32;
    const int part = blockIdx.y;
    const float* X = part ? key : query;
    float* out = part ? g_kp : g_qp;
    const int woff = part * 128;

    unsigned long long acc2[4][2];
    if (part == 0) {
        float4 bv = *reinterpret_cast<const float4*>(b1 + tx * 4);
        unsigned long long b01 = f32x2_pack(bv.x, bv.y);
        unsigned long long b23 = f32x2_pack(bv.z, bv.w);
        #pragma unroll
        for (int i = 0; i < 4; i++) { acc2[i][0] = b01; acc2[i][1] = b23; }
    } else {
        #pragma unroll
        for (int i = 0; i < 4; i++) { acc2[i][0] = 0ULL; acc2[i][1] = 0ULL; }
    }

    const int xr = tid >> 3, xk = (tid & 7) * 4;

    float4 xreg = *reinterpret_cast<const float4*>(X + (size_t)(R0 + xr) * 128 + xk);
    float4 wreg[4];
    #pragma unroll
    for (int j = 0; j < 4; j++) {
        int idx = tid + j * 256;
        int h = idx >> 3, k4 = (idx & 7) * 4;
        wreg[j] = *reinterpret_cast<const float4*>(W1 + (size_t)h * 256 + woff + k4);
    }

    for (int kc = 0; kc < 4; kc++) {
        xs[xr][xk + 0] = xreg.x; xs[xr][xk + 1] = xreg.y;
        xs[xr][xk + 2] = xreg.z; xs[xr][xk + 3] = xreg.w;
        #pragma unroll
        for (int j = 0; j < 4; j++) {
            int idx = tid + j * 256;
            int h = idx >> 3, k4 = (idx & 7) * 4;
            ws[k4 + 0][h] = wreg[j].x; ws[k4 + 1][h] = wreg[j].y;
            ws[k4 + 2][h] = wreg[j].z; ws[k4 + 3][h] = wreg[j].w;
        }
        __syncthreads();

        if (kc < 3) {
            xreg = *reinterpret_cast<const float4*>(
                X + (size_t)(R0 + xr) * 128 + (kc + 1) * 32 + xk);
            #pragma unroll
            for (int j = 0; j < 4; j++) {
                int idx = tid + j * 256;
                int h = idx >> 3, k4 = (idx & 7) * 4;
                wreg[j] = *reinterpret_cast<const float4*>(
                    W1 + (size_t)h * 256 + woff + (kc + 1) * 32 + k4);
            }
        }

        #pragma unroll 8
        for (int k = 0; k < 32; k++) {
            ulonglong2 wv2 = *reinterpret_cast<const ulonglong2*>(&ws[k][tx * 4]);
            #pragma unroll
            for (int i = 0; i < 4; i++) {
                float xv = xs[ty + 8 * i][k];
                unsigned long long xx = f32x2_pack(xv, xv);
                acc2[i][0] = f32x2_fma(wv2.x, xx, acc2[i][0]);
                acc2[i][1] = f32x2_fma(wv2.y, xx, acc2[i][1]);
            }
        }
        __syncthreads();
    }

    float4 accf[4];
    #pragma unroll
    for (int i = 0; i < 4; i++) {
        f32x2_unpack(acc2[i][0], accf[i].x, accf[i].y);
        f32x2_unpack(acc2[i][1], accf[i].z, accf[i].w);
        int r = R0 + ty + 8 * i;
        *reinterpret_cast<float4*>(out + (size_t)r * 128 + tx * 4) = accf[i];
    }

    float4 w2v = *reinterpret_cast<const float4*>(W2 + tx * 4);
    #pragma unroll
    for (int i = 0; i < 4; i++) {
        float ps = accf[i].x * w2v.x + accf[i].y * w2v.y
                 + accf[i].z * w2v.z + accf[i].w * w2v.w;
        #pragma unroll
        for (int off = 16; off >= 1; off >>= 1)
            ps += __shfl_xor_sync(0xffffffffu, ps, off);
        if (tx == 0) {
            int r = R0 + ty + 8 * i;
            if (part == 0) {
                g_a[r] = 0.5f * ps + b2[0];
            } else {
                g_c[r] = k_mask[r] ? 0.5f * ps : -1e30f;
            }
        }
    }
}

// ================= Kernel 2: fused scoring + exp + value accum (compacted) ===
// Identical math to the 82.4us fused kernel, but s and t iterate over the
// COMPACTED active lists (~50% each => ~4x less work). Warp covers 8 active s
// (sets A/B); tt groups of 8 with butterfly transpose-reduce. tz-th block
// processes chunks c = tz, tz+8, ... of 32 compacted t's.
__global__ __launch_bounds__(256, 2) void attn_kernel(
    const float* __restrict__ value, const float* __restrict__ W2)
{
    __shared__ float kp_s[32 * 128];    // permuted: chunk (hc, ib) at slot ib*8+hc
    __shared__ float v_s [32 * 128];
    __shared__ float c_s [32];
    __shared__ int   s_ids[64];

    const int tid = threadIdx.x;
    const int warp = tid >> 5, lane = tid & 31;
    const int s_local = lane >> 3, hc = lane & 7;
    const int stile = blockIdx.x, tz = blockIdx.y, b = blockIdx.z;

    const int ns = g_ns[b], nt = g_nt[b];
    if (stile * 64 >= ns) return;

    if (tid < 64) s_ids[tid] = g_slist[b * S1_ + stile * 64 + tid];
    __syncthreads();

    const int iiA = warp * 8 + s_local;           // offset within this s-tile
    const bool vA = stile * 64 + iiA < ns;
    const bool vB = stile * 64 + iiA + 4 < ns;
    const int sA = s_ids[iiA];
    const int sB = s_ids[iiA + 4];
    const int rowA = b * S1_ + sA;
    const int rowB = b * S1_ + sB;

    unsigned long long qpA2[8], qpB2[8], w2p[8];
    {
        const float4* qrowA = reinterpret_cast<const float4*>(
            g_qp + (size_t)rowA * HID_ + hc * 16);
        const float4* qrowB = reinterpret_cast<const float4*>(
            g_qp + (size_t)rowB * HID_ + hc * 16);
        #pragma unroll
        for (int i = 0; i < 4; i++) {
            float4 qa = qrowA[i];
            qpA2[2 * i]     = f32x2_pack(qa.x, qa.y);
            qpA2[2 * i + 1] = f32x2_pack(qa.z, qa.w);
            float4 qb = qrowB[i];
            qpB2[2 * i]     = f32x2_pack(qb.x, qb.y);
            qpB2[2 * i + 1] = f32x2_pack(qb.z, qb.w);
            float4 w = *reinterpret_cast<const float4*>(W2 + hc * 16 + i * 4);
            w2p[2 * i]     = f32x2_pack(0.5f * w.x, 0.5f * w.y);
            w2p[2 * i + 1] = f32x2_pack(0.5f * w.z, 0.5f * w.w);
        }
    }
    const float aA = g_a[rowA];
    const float aB = g_a[rowB];

    unsigned long long vaccA[8], vaccB[8];
    #pragma unroll
    for (int i = 0; i < 8; i++) { vaccA[i] = 0ULL; vaccB[i] = 0ULL; }
    float denA = 0.f, denB = 0.f;        // lane-distributed over tt (disjoint)

    const unsigned long long ABS2 = 0x7FFFFFFF7FFFFFFFULL;
    const int bit0 = hc & 1, bit1 = (hc >> 1) & 1, bit2 = (hc >> 2) & 1;
    const int bcast = lane & 24;
    const int* tlist = g_tlist + b * S2_;

    for (int c = tz; c * 32 < nt; c += TSPLIT) {
        const int jb = c * 32;
        __syncthreads();
        // cooperative gather of kp/v rows for 32 compacted t's (permuted slots)
        #pragma unroll
        for (int j = 0; j < 4; j++) {
            int idx = tid + j * 256;            // 0..1023 float4s
            int tt = idx >> 5, l = idx & 31;    // tt uniform across the warp
            int t = tlist[jb + tt];             // padded with 0 beyond nt
            int h4 = ((l & 7) << 2) | (l >> 3); // inverse of slot permutation
            const float4* krow = reinterpret_cast<const float4*>(
                g_kp + (size_t)(b * S2_ + t) * HID_);
            const float4* vrow = reinterpret_cast<const float4*>(
                value + (size_t)(b * S2_ + t) * HD_);
            reinterpret_cast<float4*>(kp_s)[tt * 32 + l] = krow[h4];
            reinterpret_cast<float4*>(v_s )[tt * 32 + l] = vrow[h4];
        }
        if (tid < 32) {
            int j = jb + tid;
            c_s[tid] = (j < nt) ? g_c[b * S2_ + tlist[j]] : -1e30f;
        }
        __syncthreads();

        #pragma unroll 1
        for (int g = 0; g < 4; g++) {
            // ---- score partials for 8 tt; butterfly stage 1 fused ----------
            float rA[4], rB[4];
            #pragma unroll
            for (int k = 0; k < 4; k++) {
                float m0A, m0B, m1A, m1B;
                #pragma unroll
                for (int half = 0; half < 2; half++) {
                    const float* kprow = kp_s + (g * 8 + 2 * k + half) * 128;
                    unsigned long long a0 = 0ULL, a1 = 0ULL, b0 = 0ULL, b1 = 0ULL;
                    #pragma unroll
                    for (int ib = 0; ib < 4; ib++) {
                        ulonglong2 kv = *reinterpret_cast<const ulonglong2*>(
                            kprow + ib * 32 + hc * 4);
                        unsigned long long xA01 = f32x2_add(qpA2[2 * ib],     kv.x) & ABS2;
                        unsigned long long xA23 = f32x2_add(qpA2[2 * ib + 1], kv.y) & ABS2;
                        unsigned long long xB01 = f32x2_add(qpB2[2 * ib],     kv.x) & ABS2;
                        unsigned long long xB23 = f32x2_add(qpB2[2 * ib + 1], kv.y) & ABS2;
                        a0 = f32x2_fma(xA01, w2p[2 * ib],     a0);
                        a1 = f32x2_fma(xA23, w2p[2 * ib + 1], a1);
                        b0 = f32x2_fma(xB01, w2p[2 * ib],     b0);
                        b1 = f32x2_fma(xB23, w2p[2 * ib + 1], b1);
                    }
                    float la, ha, lb, hb;
                    f32x2_unpack(f32x2_add(a0, a1), la, ha);
                    f32x2_unpack(f32x2_add(b0, b1), lb, hb);
                    if (half == 0) { m0A = la + ha; m0B = lb + hb; }
                    else           { m1A = la + ha; m1B = lb + hb; }
                }
                // stage 1 (xor 1): keep tt with bit0(tt) == bit0(hc)
                rA[k] = bfly_step(bit0 ? m1A : m0A, bit0 ? m0A : m1A, 1);
                rB[k] = bfly_step(bit0 ? m1B : m0B, bit0 ? m0B : m1B, 1);
            }
            // stage 2 (xor 2)
            float sA2[2], sB2[2];
            #pragma unroll
            for (int k = 0; k < 2; k++) {
                sA2[k] = bfly_step(bit1 ? rA[2 * k + 1] : rA[2 * k],
                                   bit1 ? rA[2 * k] : rA[2 * k + 1], 2);
                sB2[k] = bfly_step(bit1 ? rB[2 * k + 1] : rB[2 * k],
                                   bit1 ? rB[2 * k] : rB[2 * k + 1], 2);
            }
            // stage 3 (xor 4): lane hc now holds score for tt = g*8 + hc
            float scA = bfly_step(bit2 ? sA2[1] : sA2[0],
                                  bit2 ? sA2[0] : sA2[1], 4);
            float scB = bfly_step(bit2 ? sB2[1] : sB2[0],
                                  bit2 ? sB2[0] : sB2[1], 4);

            float ct = c_s[g * 8 + hc];
            float pA = __expf(scA + aA + ct);   // ct = -1e30 on padding => p = 0
            float pB = __expf(scB + aB + ct);
            denA += pA;
            denB += pB;

            // ---- broadcast p per tt and accumulate value -------------------
            #pragma unroll
            for (int j = 0; j < 8; j++) {
                float pAj = __shfl_sync(0xffffffffu, pA, bcast + j);
                float pBj = __shfl_sync(0xffffffffu, pB, bcast + j);
                unsigned long long pA2 = f32x2_pack(pAj, pAj);
                unsigned long long pB2 = f32x2_pack(pBj, pBj);
                const float* vrow2 = v_s + (g * 8 + j) * 128;
                #pragma unroll
                for (int m = 0; m < 4; m++) {
                    ulonglong2 vv = *reinterpret_cast<const ulonglong2*>(
                        vrow2 + m * 32 + hc * 4);
                    vaccA[2 * m]     = f32x2_fma(vv.x, pA2, vaccA[2 * m]);
                    vaccA[2 * m + 1] = f32x2_fma(vv.y, pA2, vaccA[2 * m + 1]);
                    vaccB[2 * m]     = f32x2_fma(vv.x, pB2, vaccB[2 * m]);
                    vaccB[2 * m + 1] = f32x2_fma(vv.y, pB2, vaccB[2 * m + 1]);
                }
            }
        }
    }

    // reduce lane-distributed denominators across the 8 hc lanes
    #pragma unroll
    for (int off = 1; off <= 4; off <<= 1) {
        denA += __shfl_xor_sync(0xffffffffu, denA, off);
        denB += __shfl_xor_sync(0xffffffffu, denB, off);
    }

    // write partials at the REAL s index (guarded for tile padding)
    if (vA) {
        float* outA = g_pout + ((size_t)(tz * B_ + b) * S1_ + sA) * HD_ + hc * 16;
        #pragma unroll
        for (int m = 0; m < 4; m++) {
            float x0, x1, x2, x3;
            f32x2_unpack(vaccA[2 * m],     x0, x1);
            f32x2_unpack(vaccA[2 * m + 1], x2, x3);
            *reinterpret_cast<float4*>(outA + m * 4) = make_float4(x0, x1, x2, x3);
        }
        if (hc == 0) g_pden[(size_t)(tz * B_ + b) * S1_ + sA] = denA;
    }
    if (vB) {
        float* outB = g_pout + ((size_t)(tz * B_ + b) * S1_ + sB) * HD_ + hc * 16;
        #pragma unroll
        for (int m = 0; m < 4; m++) {
            float x0, x1, x2, x3;
            f32x2_unpack(vaccB[2 * m],     x0, x1);
            f32x2_unpack(vaccB[2 * m + 1], x2, x3);
            *reinterpret_cast<float4*>(outB + m * 4) = make_float4(x0, x1, x2, x3);
        }
        if (hc == 0) g_pden[(size_t)(tz * B_ + b) * S1_ + sB] = denB;
    }
}

// ================= Kernel 3: reduce partials + normalize + q_mask ============
__global__ __launch_bounds__(256) void reduce_kernel(
    const int* __restrict__ q_mask, float* __restrict__ out)
{
    int idx = blockIdx.x * 256 + threadIdx.x;   // float4 index
    if (idx >= B_ * S1_ * (HD_ / 4)) return;
    int d4 = idx & 31;
    int row = idx >> 5;                          // b*S1 + s
    if (q_mask[row] == 0) {                      // masked row: exact zero output
        reinterpret_cast<float4*>(out)[idx] = make_float4(0.f, 0.f, 0.f, 0.f);
        return;
    }
    float4 sum = make_float4(0.f, 0.f, 0.f, 0.f);
    float dsum = 0.f;
    #pragma unroll
    for (int k = 0; k < TSPLIT; k++) {
        float4 p = reinterpret_cast<const float4*>(g_pout)
                       [((size_t)k * B_ * S1_ + row) * 32 + d4];
        sum.x += p.x; sum.y += p.y; sum.z += p.z; sum.w += p.w;
        dsum += g_pden[(size_t)k * B_ * S1_ + row];
    }
    float scale = 1.0f / fmaxf(dsum, 2e-15f);
    reinterpret_cast<float4*>(out)[idx] =
        make_float4(sum.x * scale, sum.y * scale, sum.z * scale, sum.w * scale);
}

// ================= launch ====================================================
extern "C" void kernel_launch(void* const* d_in, const int* in_sizes, int n_in,
                              void* d_out, int out_size)
{
    const float* query  = (const float*)d_in[0];
    const float* key    = (const float*)d_in[1];
    const float* value  = (const float*)d_in[2];
    const int*   q_mask = (const int*)  d_in[3];
    const int*   k_mask = (const int*)  d_in[4];
    const float* W1     = (const float*)d_in[5];
    const float* b1     = (const float*)d_in[6];
    const float* W2     = (const float*)d_in[7];
    const float* b2     = (const float*)d_in[8];
    float* out = (float*)d_out;

    compact_kernel<<<B_, 512>>>(q_mask, k_mask);
    proj_kernel  <<<dim3(128, 2), 256>>>(query, key, W1, b1, W2, b2, k_mask);
    attn_kernel  <<<dim3(S1_ / 64, TSPLIT, B_), 256>>>(value, W2);
    reduce_kernel<<<(B_ * S1_ * (HD_ / 4) + 255) / 256, 256>>>(q_mask, out);
}